// round 6
// baseline (speedup 1.0000x reference)
#include <cuda_runtime.h>
#include <stdint.h>

#define N_NODES 10000
#define D 256
#define ROW_WORDS 320   // ceil(10000/32)=313, padded to 320 (1280 B/row)

// Scratch (device globals; no allocation allowed)
__device__ __align__(16) unsigned int g_bitmap[N_NODES * ROW_WORDS];  // 12.8 MB
__device__ float g_dinv[N_NODES];
__device__ __align__(16) float g_zs[N_NODES * D];   // dinv[j] * (x@W)[j,:]
__device__ int g_mode;   // 0 = int32 edge layout, 1 = raw int64 layout

// ---------------------------------------------------------------------------
// Detect whether edge_index arrived as int32 (harness-converted) or raw int64.
// int64 little-endian read as int32: every odd word is the (zero) hi half.
__global__ void detect_mode_kernel(const int* __restrict__ ei, int n_words) {
    __shared__ unsigned int s_or[16];
    int t = threadIdx.x;                      // 512 threads
    unsigned int v = 0;
    int idx = 2 * t + 1;
    if (idx < n_words) v = (unsigned int)ei[idx];
    #pragma unroll
    for (int o = 16; o > 0; o >>= 1) v |= __shfl_down_sync(0xffffffffu, v, o);
    if ((t & 31) == 0) s_or[t >> 5] = v;
    __syncthreads();
    if (t == 0) {
        unsigned int r = 0;
        #pragma unroll
        for (int w = 0; w < 16; w++) r |= s_or[w];
        g_mode = (r == 0u) ? 1 : 0;           // all-zero odd words => int64
    }
}

__global__ void zero_bitmap_kernel() {
    int idx = blockIdx.x * blockDim.x + threadIdx.x;
    const int total = N_NODES * ROW_WORDS / 4;
    uint4 z = make_uint4(0u, 0u, 0u, 0u);
    for (int i = idx; i < total; i += gridDim.x * blockDim.x)
        ((uint4*)g_bitmap)[i] = z;
}

// One thread per edge; idempotent atomicOr gives exact dedup ("set, not add")
__global__ void set_edges_kernel(const int* __restrict__ ei, int E) {
    int e = blockIdx.x * blockDim.x + threadIdx.x;
    if (e >= E) return;
    int s, d;
    if (g_mode) {             // raw int64: lo words at even offsets
        s = ei[2 * e];
        d = ei[2 * E + 2 * e];
    } else {                  // int32: [2][E] row-major
        s = ei[e];
        d = ei[E + e];
    }
    if ((unsigned)s >= N_NODES || (unsigned)d >= N_NODES) return;  // never trap
    atomicOr(&g_bitmap[s * ROW_WORDS + (d >> 5)], 1u << (d & 31));
    atomicOr(&g_bitmap[d * ROW_WORDS + (s >> 5)], 1u << (s & 31));
}

// One warp per row: deg = popcount(row bits) + 1 (self-loop from +I)
__global__ void dinv_kernel() {
    int warp = (blockIdx.x * blockDim.x + threadIdx.x) >> 5;
    int lane = threadIdx.x & 31;
    if (warp >= N_NODES) return;
    const unsigned int* row = &g_bitmap[warp * ROW_WORDS];
    int cnt = 0;
    #pragma unroll
    for (int w = 0; w < ROW_WORDS / 32; w++)
        cnt += __popc(row[lane + w * 32]);
    #pragma unroll
    for (int o = 16; o > 0; o >>= 1)
        cnt += __shfl_down_sync(0xffffffffu, cnt, o);
    if (lane == 0) g_dinv[warp] = rsqrtf((float)(cnt + 1));
}

// ---------------------------------------------------------------------------
// GEMM: zs[m, n] = dinv[m] * sum_k x[m,k] * W[k,n]
// BM=64, BN=64, BK=32, 256 threads, 4x4 per thread.
#define BM 64
#define BN 64
#define BK 32

__global__ __launch_bounds__(256) void gemm_xw_kernel(
    const float* __restrict__ x, const float* __restrict__ w)
{
    __shared__ float  As[BM][BK + 1];      // scalar-accessed, +1 pad
    __shared__ float4 Bs[BK][BN / 4];      // typed float4 => aligned
    int tid = threadIdx.x;
    int tx = tid & 15;          // N dir (16)
    int ty = tid >> 4;          // M dir (16)
    int bm = blockIdx.x * BM;
    int bn = blockIdx.y * BN;

    float acc[4][4];
    #pragma unroll
    for (int i = 0; i < 4; i++)
        #pragma unroll
        for (int j = 0; j < 4; j++) acc[i][j] = 0.0f;

    for (int kb = 0; kb < D; kb += BK) {
        // A tile: 64x32 floats = 512 float4, 2 per thread
        #pragma unroll
        for (int t = 0; t < 2; t++) {
            int lin = tid + t * 256;
            int row = lin >> 3;        // 0..63
            int k4  = lin & 7;         // 0..7
            float4 v = make_float4(0.f, 0.f, 0.f, 0.f);
            if (bm + row < N_NODES)
                v = *(const float4*)&x[(size_t)(bm + row) * D + kb + k4 * 4];
            As[row][k4 * 4 + 0] = v.x;
            As[row][k4 * 4 + 1] = v.y;
            As[row][k4 * 4 + 2] = v.z;
            As[row][k4 * 4 + 3] = v.w;
        }
        // B tile: 32x64 floats = 512 float4, 2 per thread
        #pragma unroll
        for (int t = 0; t < 2; t++) {
            int lin = tid + t * 256;
            int row = lin >> 4;        // 0..31
            int n4  = lin & 15;        // 0..15
            Bs[row][n4] = *(const float4*)&w[(size_t)(kb + row) * D + bn + n4 * 4];
        }
        __syncthreads();

        #pragma unroll
        for (int kk = 0; kk < BK; kk++) {
            float a[4];
            #pragma unroll
            for (int i = 0; i < 4; i++) a[i] = As[ty * 4 + i][kk];
            float4 b = Bs[kk][tx];
            #pragma unroll
            for (int i = 0; i < 4; i++) {
                acc[i][0] += a[i] * b.x;
                acc[i][1] += a[i] * b.y;
                acc[i][2] += a[i] * b.z;
                acc[i][3] += a[i] * b.w;
            }
        }
        __syncthreads();
    }

    #pragma unroll
    for (int i = 0; i < 4; i++) {
        int m = bm + ty * 4 + i;
        if (m < N_NODES) {
            float dv = g_dinv[m];
            float4 o = make_float4(acc[i][0] * dv, acc[i][1] * dv,
                                   acc[i][2] * dv, acc[i][3] * dv);
            *(float4*)&g_zs[(size_t)m * D + bn + tx * 4] = o;
        }
    }
}

// ---------------------------------------------------------------------------
// SpMM over the bitmap: out[i,d] = dinv[i] * (sum_{bit(i,j)} zs[j,d] + zs[i,d])
// One CTA per row, 256 threads = one per output dim.
#define CHUNK_WORDS 128
#define CAP (CHUNK_WORDS * 32)

__global__ __launch_bounds__(256) void spmm_kernel(float* __restrict__ out) {
    __shared__ int s_idx[CAP];
    __shared__ int s_cnt;
    int i = blockIdx.x;
    int d = threadIdx.x;
    const unsigned int* row = &g_bitmap[i * ROW_WORDS];

    float acc0 = 0.f, acc1 = 0.f, acc2 = 0.f, acc3 = 0.f;

    for (int cw = 0; cw < ROW_WORDS; cw += CHUNK_WORDS) {
        if (d == 0) s_cnt = 0;
        __syncthreads();
        if (d < CHUNK_WORDS) {
            int w = cw + d;
            unsigned int bits = (w < ROW_WORDS) ? row[w] : 0u;
            while (bits) {
                int b = __ffs(bits) - 1;
                bits &= bits - 1;
                int pos = atomicAdd(&s_cnt, 1);
                s_idx[pos] = (w << 5) + b;
            }
        }
        __syncthreads();
        int nb = s_cnt;
        int k = 0;
        for (; k + 4 <= nb; k += 4) {
            int j0 = s_idx[k + 0];
            int j1 = s_idx[k + 1];
            int j2 = s_idx[k + 2];
            int j3 = s_idx[k + 3];
            acc0 += g_zs[(size_t)j0 * D + d];
            acc1 += g_zs[(size_t)j1 * D + d];
            acc2 += g_zs[(size_t)j2 * D + d];
            acc3 += g_zs[(size_t)j3 * D + d];
        }
        for (; k < nb; k++) {
            int j = s_idx[k];
            acc0 += g_zs[(size_t)j * D + d];
        }
        __syncthreads();
    }

    float dv = g_dinv[i];
    float self = g_zs[(size_t)i * D + d];
    out[(size_t)i * D + d] = dv * ((acc0 + acc1) + (acc2 + acc3) + self);
}

// ---------------------------------------------------------------------------
extern "C" void kernel_launch(void* const* d_in, const int* in_sizes, int n_in,
                              void* d_out, int out_size) {
    const float* x = (const float*)d_in[0];
    const int* ei = (const int*)d_in[1];
    const float* w = (const float*)d_in[2];
    float* out = (float*)d_out;
    int E = in_sizes[1] / 2;

    detect_mode_kernel<<<1, 512>>>(ei, 2 * E);
    zero_bitmap_kernel<<<1024, 256>>>();
    set_edges_kernel<<<(E + 255) / 256, 256>>>(ei, E);
    dinv_kernel<<<(N_NODES * 32 + 255) / 256, 256>>>();

    dim3 ggrid((N_NODES + BM - 1) / BM, D / BN);
    gemm_xw_kernel<<<ggrid, 256>>>(x, w);

    spmm_kernel<<<N_NODES, 256>>>(out);
}

// round 9
// speedup vs baseline: 1.0686x; 1.0686x over previous
#include <cuda_runtime.h>
#include <cuda_bf16.h>
#include <mma.h>
#include <stdint.h>

using namespace nvcuda;

#define N_NODES 10000
#define D 256
#define ROW_WORDS 320   // ceil(10000/32)=313, padded to 320 (1280 B/row)

// ---------------- scratch (device globals; no allocation allowed) ----------
__device__ __align__(16) unsigned int g_bitmap[N_NODES * ROW_WORDS];  // 12.8 MB
__device__ float g_dinv[N_NODES];
__device__ __align__(16) float g_zs[N_NODES * D];        // dinv[j] * (x@W)[j,:]
__device__ __align__(16) __nv_bfloat16 g_wh[D * D];      // W hi  [k][n]
__device__ __align__(16) __nv_bfloat16 g_wl[D * D];      // W lo  [k][n]
__device__ int g_mode;   // 0 = int32 edge layout, 1 = raw int64 layout

// ---------------------------------------------------------------------------
__global__ void detect_mode_kernel(const int* __restrict__ ei, int n_words) {
    __shared__ unsigned int s_or[16];
    int t = threadIdx.x;                      // 512 threads
    unsigned int v = 0;
    int idx = 2 * t + 1;
    if (idx < n_words) v = (unsigned int)ei[idx];
    #pragma unroll
    for (int o = 16; o > 0; o >>= 1) v |= __shfl_down_sync(0xffffffffu, v, o);
    if ((t & 31) == 0) s_or[t >> 5] = v;
    __syncthreads();
    if (t == 0) {
        unsigned int r = 0;
        #pragma unroll
        for (int w = 0; w < 16; w++) r |= s_or[w];
        g_mode = (r == 0u) ? 1 : 0;           // all-zero odd words => int64
    }
}

__global__ void zero_bitmap_kernel() {
    int idx = blockIdx.x * blockDim.x + threadIdx.x;
    const int total = N_NODES * ROW_WORDS / 4;
    uint4 z = make_uint4(0u, 0u, 0u, 0u);
    for (int i = idx; i < total; i += gridDim.x * blockDim.x)
        ((uint4*)g_bitmap)[i] = z;
}

__global__ void set_edges_kernel(const int* __restrict__ ei, int E) {
    int e = blockIdx.x * blockDim.x + threadIdx.x;
    if (e >= E) return;
    int s, d;
    if (g_mode) { s = ei[2 * e];  d = ei[2 * E + 2 * e]; }
    else        { s = ei[e];      d = ei[E + e]; }
    if ((unsigned)s >= N_NODES || (unsigned)d >= N_NODES) return;
    atomicOr(&g_bitmap[s * ROW_WORDS + (d >> 5)], 1u << (d & 31));
    atomicOr(&g_bitmap[d * ROW_WORDS + (s >> 5)], 1u << (s & 31));
}

// One warp per row, uint4 loads for MLP: deg = popcount(row) + 1
__global__ void dinv_kernel() {
    int warp = (blockIdx.x * blockDim.x + threadIdx.x) >> 5;
    int lane = threadIdx.x & 31;
    if (warp >= N_NODES) return;
    const uint4* row = (const uint4*)&g_bitmap[warp * ROW_WORDS];  // 80 uint4
    int cnt = 0;
    #pragma unroll
    for (int t = 0; t < 3; t++) {
        int idx = lane + t * 32;
        if (idx < 80) {
            uint4 v = row[idx];
            cnt += __popc(v.x) + __popc(v.y) + __popc(v.z) + __popc(v.w);
        }
    }
    #pragma unroll
    for (int o = 16; o > 0; o >>= 1)
        cnt += __shfl_down_sync(0xffffffffu, cnt, o);
    if (lane == 0) g_dinv[warp] = rsqrtf((float)(cnt + 1));
}

// ---------------------------------------------------------------------------
// W prep: bf16 hi/lo split, natural [k][n] layout (wmma matrix_b row-major).
__global__ void prep_w_kernel(const float* __restrict__ w) {
    int idx = blockIdx.x * blockDim.x + threadIdx.x;   // 65536 elems
    float v = w[idx];
    unsigned short hb = __bfloat16_as_ushort(__float2bfloat16(v));
    float hf = __uint_as_float(((unsigned int)hb) << 16);
    unsigned short lb = __bfloat16_as_ushort(__float2bfloat16(v - hf));
    g_wh[idx] = __ushort_as_bfloat16(hb);
    g_wl[idx] = __ushort_as_bfloat16(lb);
}

// ---------------------------------------------------------------------------
// wmma bf16 GEMM (3-term split): zs[m,n] = dinv[m] * sum_k x[m,k]*W[k,n]
// CTA tile 128(M) x 128(N), BK=32, 8 warps (2 M x 4 N), warp tile 64x32.
#define LDA 40    // 128 x 40 bf16 (80 B/row, 16B-mult)
#define LDB 136   // 32 x 136 bf16 (272 B/row)
#define LDC 132   // 128 x 132 f32 (528 B/row)
#define SM_AH 0
#define SM_AL 10240
#define SM_BH 20480
#define SM_BL 29184
#define SMEM_MAIN 37888
#define SMEM_GEMM 67584   // epilogue C reuses from offset 0 (128*132*4)

__global__ __launch_bounds__(256) void gemm_wmma_kernel(const float* __restrict__ x) {
    extern __shared__ char smem[];
    __nv_bfloat16* sAh = (__nv_bfloat16*)(smem + SM_AH);
    __nv_bfloat16* sAl = (__nv_bfloat16*)(smem + SM_AL);
    __nv_bfloat16* sBh = (__nv_bfloat16*)(smem + SM_BH);
    __nv_bfloat16* sBl = (__nv_bfloat16*)(smem + SM_BL);
    float* sC = (float*)smem;

    int tid = threadIdx.x;
    int wid = tid >> 5;
    int warp_m = wid & 1;        // 0..1  (64 rows)
    int warp_n = wid >> 1;       // 0..3  (32 cols)
    int bm = blockIdx.x * 128;
    int bn = blockIdx.y * 128;

    wmma::fragment<wmma::accumulator, 16, 16, 16, float> acc[4][2];
    #pragma unroll
    for (int mi = 0; mi < 4; mi++)
        #pragma unroll
        for (int ni = 0; ni < 2; ni++)
            wmma::fill_fragment(acc[mi][ni], 0.0f);

    for (int k0 = 0; k0 < D; k0 += 32) {
        // A tile: 128 x 32 fp32 -> split bf16 (4 float4 per thread)
        #pragma unroll
        for (int t = 0; t < 4; t++) {
            int lin = tid + t * 256;
            int row = lin >> 3, c4 = lin & 7;
            int m = bm + row;
            float4 v = make_float4(0.f, 0.f, 0.f, 0.f);
            if (m < N_NODES) v = *(const float4*)&x[(size_t)m * D + k0 + c4 * 4];
            unsigned short h0 = __bfloat16_as_ushort(__float2bfloat16(v.x));
            unsigned short h1 = __bfloat16_as_ushort(__float2bfloat16(v.y));
            unsigned short h2 = __bfloat16_as_ushort(__float2bfloat16(v.z));
            unsigned short h3 = __bfloat16_as_ushort(__float2bfloat16(v.w));
            float f0 = __uint_as_float((unsigned)h0 << 16);
            float f1 = __uint_as_float((unsigned)h1 << 16);
            float f2 = __uint_as_float((unsigned)h2 << 16);
            float f3 = __uint_as_float((unsigned)h3 << 16);
            unsigned short l0 = __bfloat16_as_ushort(__float2bfloat16(v.x - f0));
            unsigned short l1 = __bfloat16_as_ushort(__float2bfloat16(v.y - f1));
            unsigned short l2 = __bfloat16_as_ushort(__float2bfloat16(v.z - f2));
            unsigned short l3 = __bfloat16_as_ushort(__float2bfloat16(v.w - f3));
            unsigned long long hh = (unsigned long long)h0 | ((unsigned long long)h1 << 16)
                                  | ((unsigned long long)h2 << 32) | ((unsigned long long)h3 << 48);
            unsigned long long ll = (unsigned long long)l0 | ((unsigned long long)l1 << 16)
                                  | ((unsigned long long)l2 << 32) | ((unsigned long long)l3 << 48);
            *(unsigned long long*)&sAh[row * LDA + c4 * 4] = hh;
            *(unsigned long long*)&sAl[row * LDA + c4 * 4] = ll;
        }
        // B tile: 32 x 128 bf16 hi/lo (2 uint4 per thread each)
        #pragma unroll
        for (int t = 0; t < 2; t++) {
            int lin = tid + t * 256;
            int kr = lin >> 4, q = lin & 15;
            int gi = (k0 + kr) * D + bn + q * 8;
            *(uint4*)&sBh[kr * LDB + q * 8] = *(const uint4*)&g_wh[gi];
            *(uint4*)&sBl[kr * LDB + q * 8] = *(const uint4*)&g_wl[gi];
        }
        __syncthreads();

        #pragma unroll
        for (int kk = 0; kk < 32; kk += 16) {
            wmma::fragment<wmma::matrix_b, 16, 16, 16, __nv_bfloat16, wmma::row_major> bh[2], bl[2];
            #pragma unroll
            for (int ni = 0; ni < 2; ni++) {
                const __nv_bfloat16* bp = &sBh[kk * LDB + warp_n * 32 + ni * 16];
                const __nv_bfloat16* lp = &sBl[kk * LDB + warp_n * 32 + ni * 16];
                wmma::load_matrix_sync(bh[ni], bp, LDB);
                wmma::load_matrix_sync(bl[ni], lp, LDB);
            }
            #pragma unroll
            for (int mi = 0; mi < 4; mi++) {
                wmma::fragment<wmma::matrix_a, 16, 16, 16, __nv_bfloat16, wmma::row_major> ah, al;
                wmma::load_matrix_sync(ah, &sAh[(warp_m * 64 + mi * 16) * LDA + kk], LDA);
                wmma::load_matrix_sync(al, &sAl[(warp_m * 64 + mi * 16) * LDA + kk], LDA);
                #pragma unroll
                for (int ni = 0; ni < 2; ni++) {
                    wmma::mma_sync(acc[mi][ni], ah, bh[ni], acc[mi][ni]);
                    wmma::mma_sync(acc[mi][ni], ah, bl[ni], acc[mi][ni]);
                    wmma::mma_sync(acc[mi][ni], al, bh[ni], acc[mi][ni]);
                }
            }
        }
        __syncthreads();
    }

    // Epilogue: frags -> smem -> scale by dinv -> g_zs
    #pragma unroll
    for (int mi = 0; mi < 4; mi++)
        #pragma unroll
        for (int ni = 0; ni < 2; ni++)
            wmma::store_matrix_sync(
                &sC[(warp_m * 64 + mi * 16) * LDC + warp_n * 32 + ni * 16],
                acc[mi][ni], LDC, wmma::mem_row_major);
    __syncthreads();

    #pragma unroll
    for (int t = 0; t < 16; t++) {
        int lin = tid + t * 256;
        int row = lin >> 5, c4 = lin & 31;
        int m = bm + row;
        if (m < N_NODES) {
            float dv = g_dinv[m];
            float4 v = *(float4*)&sC[row * LDC + c4 * 4];
            v.x *= dv; v.y *= dv; v.z *= dv; v.w *= dv;
            *(float4*)&g_zs[(size_t)m * D + bn + c4 * 4] = v;
        }
    }
}

// ---------------------------------------------------------------------------
// SpMM over the bitmap: out[i,d] = dinv[i] * (sum_{bit(i,j)} zs[j,d] + zs[i,d])
#define CHUNK_WORDS 128
#define CAP (CHUNK_WORDS * 32)

__global__ __launch_bounds__(256) void spmm_kernel(float* __restrict__ out) {
    __shared__ int s_idx[CAP];
    __shared__ int s_cnt;
    int i = blockIdx.x;
    int d = threadIdx.x;
    const unsigned int* row = &g_bitmap[i * ROW_WORDS];

    float acc0 = 0.f, acc1 = 0.f, acc2 = 0.f, acc3 = 0.f;

    for (int cw = 0; cw < ROW_WORDS; cw += CHUNK_WORDS) {
        if (d == 0) s_cnt = 0;
        __syncthreads();
        if (d < CHUNK_WORDS) {
            int w = cw + d;
            unsigned int bits = (w < ROW_WORDS) ? row[w] : 0u;
            while (bits) {
                int b = __ffs(bits) - 1;
                bits &= bits - 1;
                int pos = atomicAdd(&s_cnt, 1);
                s_idx[pos] = (w << 5) + b;
            }
        }
        __syncthreads();
        int nb = s_cnt;
        int k = 0;
        for (; k + 4 <= nb; k += 4) {
            int j0 = s_idx[k + 0];
            int j1 = s_idx[k + 1];
            int j2 = s_idx[k + 2];
            int j3 = s_idx[k + 3];
            acc0 += g_zs[(size_t)j0 * D + d];
            acc1 += g_zs[(size_t)j1 * D + d];
            acc2 += g_zs[(size_t)j2 * D + d];
            acc3 += g_zs[(size_t)j3 * D + d];
        }
        for (; k < nb; k++) {
            int j = s_idx[k];
            acc0 += g_zs[(size_t)j * D + d];
        }
        __syncthreads();
    }

    float dv = g_dinv[i];
    float self = g_zs[(size_t)i * D + d];
    out[(size_t)i * D + d] = dv * ((acc0 + acc1) + (acc2 + acc3) + self);
}

// ---------------------------------------------------------------------------
extern "C" void kernel_launch(void* const* d_in, const int* in_sizes, int n_in,
                              void* d_out, int out_size) {
    const float* x = (const float*)d_in[0];
    const int* ei = (const int*)d_in[1];
    const float* w = (const float*)d_in[2];
    float* out = (float*)d_out;
    int E = in_sizes[1] / 2;

    cudaFuncSetAttribute(gemm_wmma_kernel,
                         cudaFuncAttributeMaxDynamicSharedMemorySize, SMEM_GEMM);

    prep_w_kernel<<<D * D / 256, 256>>>(w);
    detect_mode_kernel<<<1, 512>>>(ei, 2 * E);
    zero_bitmap_kernel<<<1024, 256>>>();
    set_edges_kernel<<<(E + 255) / 256, 256>>>(ei, E);
    dinv_kernel<<<(N_NODES * 32 + 255) / 256, 256>>>();

    dim3 ggrid((N_NODES + 127) / 128, D / 128);
    gemm_wmma_kernel<<<ggrid, 256, SMEM_GEMM>>>(x);

    spmm_kernel<<<N_NODES, 256>>>(out);
}

// round 10
// speedup vs baseline: 1.3440x; 1.2576x over previous
#include <cuda_runtime.h>
#include <cuda_bf16.h>
#include <cuda_fp16.h>
#include <mma.h>
#include <stdint.h>

using namespace nvcuda;

#define N_NODES 10000
#define D 256
#define ROW_WORDS 320   // ceil(10000/32)=313, padded to 320 (1280 B/row)

// ---------------- scratch (device globals; no allocation allowed) ----------
__device__ __align__(16) unsigned int g_bitmap[N_NODES * ROW_WORDS];  // 12.8 MB
__device__ float g_dinv[N_NODES];
__device__ __align__(16) __half g_zs_h[N_NODES * D];     // fp16 dinv[j]*(x@W)[j,:]
__device__ __align__(16) __nv_bfloat16 g_wh[D * D];      // W hi  [k][n]
__device__ __align__(16) __nv_bfloat16 g_wl[D * D];      // W lo  [k][n]
__device__ int g_mode;   // 0 = int32 edge layout, 1 = raw int64 layout

// ---------------------------------------------------------------------------
__global__ void detect_mode_kernel(const int* __restrict__ ei, int n_words) {
    __shared__ unsigned int s_or[16];
    int t = threadIdx.x;                      // 512 threads
    unsigned int v = 0;
    int idx = 2 * t + 1;
    if (idx < n_words) v = (unsigned int)ei[idx];
    #pragma unroll
    for (int o = 16; o > 0; o >>= 1) v |= __shfl_down_sync(0xffffffffu, v, o);
    if ((t & 31) == 0) s_or[t >> 5] = v;
    __syncthreads();
    if (t == 0) {
        unsigned int r = 0;
        #pragma unroll
        for (int w = 0; w < 16; w++) r |= s_or[w];
        g_mode = (r == 0u) ? 1 : 0;           // all-zero odd words => int64
    }
}

__global__ void zero_bitmap_kernel() {
    int idx = blockIdx.x * blockDim.x + threadIdx.x;
    const int total = N_NODES * ROW_WORDS / 4;
    uint4 z = make_uint4(0u, 0u, 0u, 0u);
    for (int i = idx; i < total; i += gridDim.x * blockDim.x)
        ((uint4*)g_bitmap)[i] = z;
}

// 4 edges per thread, int4 vectorized loads for MLP
__global__ void set_edges_kernel(const int* __restrict__ ei, int E) {
    int t = blockIdx.x * blockDim.x + threadIdx.x;
    int base = t * 4;
    if (base >= E) return;
    int s[4], d[4];
    bool vec = ((E & 3) == 0) && (base + 3 < E);
    if (g_mode) {
        if (vec) {
            int4 a0 = ((const int4*)ei)[2 * t];
            int4 a1 = ((const int4*)ei)[2 * t + 1];
            const int* dd = ei + 2 * E;
            int4 b0 = ((const int4*)dd)[2 * t];
            int4 b1 = ((const int4*)dd)[2 * t + 1];
            s[0] = a0.x; s[1] = a0.z; s[2] = a1.x; s[3] = a1.z;
            d[0] = b0.x; d[1] = b0.z; d[2] = b1.x; d[3] = b1.z;
        } else {
            #pragma unroll
            for (int q = 0; q < 4; q++) {
                int e = base + q;
                s[q] = (e < E) ? ei[2 * e] : -1;
                d[q] = (e < E) ? ei[2 * E + 2 * e] : -1;
            }
        }
    } else {
        if (vec) {
            int4 a = ((const int4*)ei)[t];
            int4 b = ((const int4*)(ei + E))[t];
            s[0] = a.x; s[1] = a.y; s[2] = a.z; s[3] = a.w;
            d[0] = b.x; d[1] = b.y; d[2] = b.z; d[3] = b.w;
        } else {
            #pragma unroll
            for (int q = 0; q < 4; q++) {
                int e = base + q;
                s[q] = (e < E) ? ei[e] : -1;
                d[q] = (e < E) ? ei[E + e] : -1;
            }
        }
    }
    #pragma unroll
    for (int q = 0; q < 4; q++) {
        if ((unsigned)s[q] < N_NODES && (unsigned)d[q] < N_NODES) {
            atomicOr(&g_bitmap[s[q] * ROW_WORDS + (d[q] >> 5)], 1u << (d[q] & 31));
            atomicOr(&g_bitmap[d[q] * ROW_WORDS + (s[q] >> 5)], 1u << (s[q] & 31));
        }
    }
}

// One warp per row, uint4 loads for MLP: deg = popcount(row) + 1
__global__ void dinv_kernel() {
    int warp = (blockIdx.x * blockDim.x + threadIdx.x) >> 5;
    int lane = threadIdx.x & 31;
    if (warp >= N_NODES) return;
    const uint4* row = (const uint4*)&g_bitmap[warp * ROW_WORDS];  // 80 uint4
    int cnt = 0;
    #pragma unroll
    for (int t = 0; t < 3; t++) {
        int idx = lane + t * 32;
        if (idx < 80) {
            uint4 v = row[idx];
            cnt += __popc(v.x) + __popc(v.y) + __popc(v.z) + __popc(v.w);
        }
    }
    #pragma unroll
    for (int o = 16; o > 0; o >>= 1)
        cnt += __shfl_down_sync(0xffffffffu, cnt, o);
    if (lane == 0) g_dinv[warp] = rsqrtf((float)(cnt + 1));
}

// ---------------------------------------------------------------------------
// W prep: bf16 hi/lo split, natural [k][n] layout (wmma matrix_b row-major).
__global__ void prep_w_kernel(const float* __restrict__ w) {
    int idx = blockIdx.x * blockDim.x + threadIdx.x;   // 65536 elems
    float v = w[idx];
    unsigned short hb = __bfloat16_as_ushort(__float2bfloat16(v));
    float hf = __uint_as_float(((unsigned int)hb) << 16);
    unsigned short lb = __bfloat16_as_ushort(__float2bfloat16(v - hf));
    g_wh[idx] = __ushort_as_bfloat16(hb);
    g_wl[idx] = __ushort_as_bfloat16(lb);
}

// ---------------------------------------------------------------------------
// wmma bf16 GEMM (3-term split): zs[m,n] = dinv[m] * sum_k x[m,k]*W[k,n]
// CTA tile 128(M) x 128(N), BK=32, 8 warps (2 M x 4 N), warp tile 64x32.
#define LDA 40    // 128 x 40 bf16 (80 B/row, 16B-mult)
#define LDB 136   // 32 x 136 bf16 (272 B/row)
#define LDC 132   // 128 x 132 f32 (528 B/row)
#define SM_AH 0
#define SM_AL 10240
#define SM_BH 20480
#define SM_BL 29184
#define SMEM_GEMM 67584   // epilogue C reuses from offset 0 (128*132*4)

__global__ __launch_bounds__(256) void gemm_wmma_kernel(const float* __restrict__ x) {
    extern __shared__ char smem[];
    __nv_bfloat16* sAh = (__nv_bfloat16*)(smem + SM_AH);
    __nv_bfloat16* sAl = (__nv_bfloat16*)(smem + SM_AL);
    __nv_bfloat16* sBh = (__nv_bfloat16*)(smem + SM_BH);
    __nv_bfloat16* sBl = (__nv_bfloat16*)(smem + SM_BL);
    float* sC = (float*)smem;

    int tid = threadIdx.x;
    int wid = tid >> 5;
    int warp_m = wid & 1;        // 0..1  (64 rows)
    int warp_n = wid >> 1;       // 0..3  (32 cols)
    int bm = blockIdx.x * 128;
    int bn = blockIdx.y * 128;

    wmma::fragment<wmma::accumulator, 16, 16, 16, float> acc[4][2];
    #pragma unroll
    for (int mi = 0; mi < 4; mi++)
        #pragma unroll
        for (int ni = 0; ni < 2; ni++)
            wmma::fill_fragment(acc[mi][ni], 0.0f);

    for (int k0 = 0; k0 < D; k0 += 32) {
        // A tile: 128 x 32 fp32 -> split bf16 (4 float4 per thread)
        #pragma unroll
        for (int t = 0; t < 4; t++) {
            int lin = tid + t * 256;
            int row = lin >> 3, c4 = lin & 7;
            int m = bm + row;
            float4 v = make_float4(0.f, 0.f, 0.f, 0.f);
            if (m < N_NODES) v = *(const float4*)&x[(size_t)m * D + k0 + c4 * 4];
            unsigned short h0 = __bfloat16_as_ushort(__float2bfloat16(v.x));
            unsigned short h1 = __bfloat16_as_ushort(__float2bfloat16(v.y));
            unsigned short h2 = __bfloat16_as_ushort(__float2bfloat16(v.z));
            unsigned short h3 = __bfloat16_as_ushort(__float2bfloat16(v.w));
            float f0 = __uint_as_float((unsigned)h0 << 16);
            float f1 = __uint_as_float((unsigned)h1 << 16);
            float f2 = __uint_as_float((unsigned)h2 << 16);
            float f3 = __uint_as_float((unsigned)h3 << 16);
            unsigned short l0 = __bfloat16_as_ushort(__float2bfloat16(v.x - f0));
            unsigned short l1 = __bfloat16_as_ushort(__float2bfloat16(v.y - f1));
            unsigned short l2 = __bfloat16_as_ushort(__float2bfloat16(v.z - f2));
            unsigned short l3 = __bfloat16_as_ushort(__float2bfloat16(v.w - f3));
            unsigned long long hh = (unsigned long long)h0 | ((unsigned long long)h1 << 16)
                                  | ((unsigned long long)h2 << 32) | ((unsigned long long)h3 << 48);
            unsigned long long ll = (unsigned long long)l0 | ((unsigned long long)l1 << 16)
                                  | ((unsigned long long)l2 << 32) | ((unsigned long long)l3 << 48);
            *(unsigned long long*)&sAh[row * LDA + c4 * 4] = hh;
            *(unsigned long long*)&sAl[row * LDA + c4 * 4] = ll;
        }
        // B tile: 32 x 128 bf16 hi/lo (2 uint4 per thread each)
        #pragma unroll
        for (int t = 0; t < 2; t++) {
            int lin = tid + t * 256;
            int kr = lin >> 4, q = lin & 15;
            int gi = (k0 + kr) * D + bn + q * 8;
            *(uint4*)&sBh[kr * LDB + q * 8] = *(const uint4*)&g_wh[gi];
            *(uint4*)&sBl[kr * LDB + q * 8] = *(const uint4*)&g_wl[gi];
        }
        __syncthreads();

        #pragma unroll
        for (int kk = 0; kk < 32; kk += 16) {
            wmma::fragment<wmma::matrix_b, 16, 16, 16, __nv_bfloat16, wmma::row_major> bh[2], bl[2];
            #pragma unroll
            for (int ni = 0; ni < 2; ni++) {
                wmma::load_matrix_sync(bh[ni], &sBh[kk * LDB + warp_n * 32 + ni * 16], LDB);
                wmma::load_matrix_sync(bl[ni], &sBl[kk * LDB + warp_n * 32 + ni * 16], LDB);
            }
            #pragma unroll
            for (int mi = 0; mi < 4; mi++) {
                wmma::fragment<wmma::matrix_a, 16, 16, 16, __nv_bfloat16, wmma::row_major> ah, al;
                wmma::load_matrix_sync(ah, &sAh[(warp_m * 64 + mi * 16) * LDA + kk], LDA);
                wmma::load_matrix_sync(al, &sAl[(warp_m * 64 + mi * 16) * LDA + kk], LDA);
                #pragma unroll
                for (int ni = 0; ni < 2; ni++) {
                    wmma::mma_sync(acc[mi][ni], ah, bh[ni], acc[mi][ni]);
                    wmma::mma_sync(acc[mi][ni], ah, bl[ni], acc[mi][ni]);
                    wmma::mma_sync(acc[mi][ni], al, bh[ni], acc[mi][ni]);
                }
            }
        }
        __syncthreads();
    }

    // Epilogue: frags -> smem -> scale by dinv -> g_zs_h (fp16)
    #pragma unroll
    for (int mi = 0; mi < 4; mi++)
        #pragma unroll
        for (int ni = 0; ni < 2; ni++)
            wmma::store_matrix_sync(
                &sC[(warp_m * 64 + mi * 16) * LDC + warp_n * 32 + ni * 16],
                acc[mi][ni], LDC, wmma::mem_row_major);
    __syncthreads();

    #pragma unroll
    for (int t = 0; t < 16; t++) {
        int lin = tid + t * 256;
        int row = lin >> 5, c4 = lin & 31;
        int m = bm + row;
        if (m < N_NODES) {
            float dv = g_dinv[m];
            float4 v = *(float4*)&sC[row * LDC + c4 * 4];
            __half2 h01 = __floats2half2_rn(v.x * dv, v.y * dv);
            __half2 h23 = __floats2half2_rn(v.z * dv, v.w * dv);
            uint2 o;
            o.x = *(unsigned int*)&h01;
            o.y = *(unsigned int*)&h23;
            *(uint2*)&g_zs_h[(size_t)m * D + bn + c4 * 4] = o;
        }
    }
}

// ---------------------------------------------------------------------------
// SpMM over the bitmap: out[i,:] = dinv[i] * (sum_{bit(i,j)} zs[j,:] + zs[i,:])
// One CTA per row, 128 threads, half2 gathers (512 B/neighbor), fp32 accum.
#define SCHUNK 128
#define SCAP (SCHUNK * 32)

__global__ __launch_bounds__(128) void spmm_kernel(float* __restrict__ out) {
    __shared__ int s_idx[SCAP];
    __shared__ int s_cnt;
    int i = blockIdx.x;
    int t = threadIdx.x;                         // dim pair t -> dims 2t, 2t+1
    const unsigned int* row = &g_bitmap[i * ROW_WORDS];
    const __half2* zs2 = (const __half2*)g_zs_h;

    float2 a0 = {0.f, 0.f}, a1 = {0.f, 0.f}, a2 = {0.f, 0.f}, a3 = {0.f, 0.f};

    for (int cw = 0; cw < ROW_WORDS; cw += SCHUNK) {
        if (t == 0) s_cnt = 0;
        __syncthreads();
        int w = cw + t;
        unsigned int bits = (w < ROW_WORDS) ? row[w] : 0u;
        while (bits) {
            int b = __ffs(bits) - 1;
            bits &= bits - 1;
            s_idx[atomicAdd(&s_cnt, 1)] = (w << 5) + b;
        }
        __syncthreads();
        int nb = s_cnt;
        int k = 0;
        for (; k + 4 <= nb; k += 4) {
            int j0 = s_idx[k + 0];
            int j1 = s_idx[k + 1];
            int j2 = s_idx[k + 2];
            int j3 = s_idx[k + 3];
            float2 v0 = __half22float2(zs2[(size_t)j0 * 128 + t]);
            float2 v1 = __half22float2(zs2[(size_t)j1 * 128 + t]);
            float2 v2 = __half22float2(zs2[(size_t)j2 * 128 + t]);
            float2 v3 = __half22float2(zs2[(size_t)j3 * 128 + t]);
            a0.x += v0.x; a0.y += v0.y;
            a1.x += v1.x; a1.y += v1.y;
            a2.x += v2.x; a2.y += v2.y;
            a3.x += v3.x; a3.y += v3.y;
        }
        for (; k < nb; k++) {
            float2 v = __half22float2(zs2[(size_t)s_idx[k] * 128 + t]);
            a0.x += v.x; a0.y += v.y;
        }
        __syncthreads();
    }

    float2 self = __half22float2(zs2[(size_t)i * 128 + t]);
    float dv = g_dinv[i];
    float2 r;
    r.x = dv * ((a0.x + a1.x) + (a2.x + a3.x) + self.x);
    r.y = dv * ((a0.y + a1.y) + (a2.y + a3.y) + self.y);
    ((float2*)out)[(size_t)i * 128 + t] = r;
}

// ---------------------------------------------------------------------------
extern "C" void kernel_launch(void* const* d_in, const int* in_sizes, int n_in,
                              void* d_out, int out_size) {
    const float* x = (const float*)d_in[0];
    const int* ei = (const int*)d_in[1];
    const float* w = (const float*)d_in[2];
    float* out = (float*)d_out;
    int E = in_sizes[1] / 2;

    cudaFuncSetAttribute(gemm_wmma_kernel,
                         cudaFuncAttributeMaxDynamicSharedMemorySize, SMEM_GEMM);

    prep_w_kernel<<<D * D / 256, 256>>>(w);
    detect_mode_kernel<<<1, 512>>>(ei, 2 * E);
    zero_bitmap_kernel<<<1024, 256>>>();
    set_edges_kernel<<<(E / 4 + 255) / 256, 256>>>(ei, E);
    dinv_kernel<<<(N_NODES * 32 + 255) / 256, 256>>>();

    dim3 ggrid((N_NODES + 127) / 128, D / 128);
    gemm_wmma_kernel<<<ggrid, 256, SMEM_GEMM>>>(x);

    spmm_kernel<<<N_NODES, 128>>>(out);
}